// round 9
// baseline (speedup 1.0000x reference)
#include <cuda_runtime.h>

#define NB 4
#define NS 2048
#define ND 1024
#define NH 16
#define NHD 64
#define NM (NB*NS)   /* 8192 rows */

// Scratch (device globals — no runtime allocation allowed)
__device__ float g_q[NB*NH*NS*NHD];
__device__ float g_k[NB*NH*NS*NHD];
__device__ float g_v[NB*NH*NS*NHD];
__device__ float g_ctx[(size_t)NM*ND];

// Fast exp2 on the FMA pipe (avoids MUFU throughput wall: 268M exps needed).
// Degree-5 Taylor on f in [-0.5, 0.5]; max rel err ~2.4e-6. Assumes x <= 0.
__device__ __forceinline__ float fast_exp2(float x) {
    x = fmaxf(x, -126.0f);
    float r = rintf(x);
    float f = x - r;
    float p = 1.3333558e-3f;          // ln2^5/120
    p = fmaf(p, f, 9.6181291e-3f);    // ln2^4/24
    p = fmaf(p, f, 5.5504109e-2f);    // ln2^3/6
    p = fmaf(p, f, 2.4022651e-1f);    // ln2^2/2
    p = fmaf(p, f, 6.9314718e-1f);    // ln2
    p = fmaf(p, f, 1.0f);
    return p * __int_as_float(((int)r + 127) << 23);
}

// ---------------------------------------------------------------------------
// GEMM: out = X @ W^T + bias.  X:[8192,1024], W:[1024,1024] (row-major [e][d])
// HEAD_LAYOUT: write out[((b*NH + e/64)*NS + s)*64 + e%64]  (m = b*NS + s)
// else:        write out[m*ND + e]
// 128x128x16 tile, 256 threads, 8x8 per thread.
// ---------------------------------------------------------------------------
template<bool HEAD_LAYOUT>
__global__ __launch_bounds__(256)
void gemm_proj(const float* __restrict__ X, const float* __restrict__ W,
               const float* __restrict__ bias, float* __restrict__ out)
{
    __shared__ float As[16][132];   // [k][m], padded
    __shared__ float Bs[16][132];   // [k][e], padded

    const int bm = blockIdx.y * 128;
    const int bn = blockIdx.x * 128;
    const int tid = threadIdx.x;
    const int tm  = tid >> 4;        // 0..15
    const int tn  = tid & 15;        // 0..15
    const int lrow = tid >> 2;       // 0..63
    const int lcol = (tid & 3) << 2; // 0,4,8,12

    float acc[8][8];
    #pragma unroll
    for (int i = 0; i < 8; i++)
        #pragma unroll
        for (int j = 0; j < 8; j++) acc[i][j] = 0.f;

    for (int k0 = 0; k0 < ND; k0 += 16) {
        #pragma unroll
        for (int hh = 0; hh < 2; hh++) {
            int r = lrow + hh * 64;
            float4 va = *(const float4*)(X + (size_t)(bm + r) * ND + k0 + lcol);
            As[lcol+0][r] = va.x; As[lcol+1][r] = va.y;
            As[lcol+2][r] = va.z; As[lcol+3][r] = va.w;
            float4 vb = *(const float4*)(W + (size_t)(bn + r) * ND + k0 + lcol);
            Bs[lcol+0][r] = vb.x; Bs[lcol+1][r] = vb.y;
            Bs[lcol+2][r] = vb.z; Bs[lcol+3][r] = vb.w;
        }
        __syncthreads();
        #pragma unroll
        for (int k = 0; k < 16; k++) {
            float a[8], b[8];
            *(float4*)&a[0] = *(const float4*)&As[k][tm*4];
            *(float4*)&a[4] = *(const float4*)&As[k][64 + tm*4];
            *(float4*)&b[0] = *(const float4*)&Bs[k][tn*4];
            *(float4*)&b[4] = *(const float4*)&Bs[k][64 + tn*4];
            #pragma unroll
            for (int i = 0; i < 8; i++)
                #pragma unroll
                for (int j = 0; j < 8; j++)
                    acc[i][j] = fmaf(a[i], b[j], acc[i][j]);
        }
        __syncthreads();
    }

    #pragma unroll
    for (int hi = 0; hi < 2; hi++) {
        #pragma unroll
        for (int ii = 0; ii < 4; ii++) {
            int m = bm + hi * 64 + tm * 4 + ii;
            int bb = m / NS;
            int ss = m % NS;
            #pragma unroll
            for (int hj = 0; hj < 2; hj++) {
                int e0 = bn + hj * 64 + tn * 4;
                float4 o;
                o.x = acc[hi*4+ii][hj*4+0] + bias[e0+0];
                o.y = acc[hi*4+ii][hj*4+1] + bias[e0+1];
                o.z = acc[hi*4+ii][hj*4+2] + bias[e0+2];
                o.w = acc[hi*4+ii][hj*4+3] + bias[e0+3];
                if (HEAD_LAYOUT) {
                    int h  = e0 >> 6;
                    int hd = e0 & 63;
                    *(float4*)(out + (((size_t)bb * NH + h) * NS + ss) * NHD + hd) = o;
                } else {
                    *(float4*)(out + (size_t)m * ND + e0) = o;
                }
            }
        }
    }
}

// ---------------------------------------------------------------------------
// Flash-style attention, fp32, online softmax in log2 domain.
// One block = (bh, 64-query tile). 256 threads as 16x16; thread (ty,tx) owns
// a 4x4 score micro-tile (q=ty*4+i, k=tx*4+j) and the ctx micro-tile
// (q=ty*4+i, hd=tx*4+j). P rows are produced & consumed within one warp.
// ---------------------------------------------------------------------------
#define SMEM_ATTN ((64*68*2 + 64*64*2) * 4)   /* 67584 bytes */

__global__ __launch_bounds__(256)
void attn_kernel(const float* __restrict__ Qg_, const float* __restrict__ Kg_,
                 const float* __restrict__ Vg_, float* __restrict__ Og)
{
    extern __shared__ float smf[];
    float* Qs = smf;                // [64 hd][68]  (hd-major, padded)
    float* Ks = Qs + 64 * 68;       // [64 hd][68]
    float* Vs = Ks + 64 * 68;       // [64 k ][64]  (natural)
    float* Ps = Vs + 64 * 64;       // [64 q ][64]

    const int bh = blockIdx.y;
    const int q0 = blockIdx.x * 64;
    const float* Qg = Qg_ + ((size_t)bh * NS + q0) * NHD;
    const float* Kg = Kg_ + (size_t)bh * NS * NHD;
    const float* Vg = Vg_ + (size_t)bh * NS * NHD;

    const int tid = threadIdx.x;
    const int ty = tid >> 4;
    const int tx = tid & 15;

    // Pre-scale Q by (1/sqrt(HD)) * log2(e) so softmax runs in exp2 domain.
    const float qsc = 0.125f * 1.44269504088896340736f;

    // Load Q tile, transposed to hd-major
    #pragma unroll
    for (int it = 0; it < 4; it++) {
        int i = tid + it * 256;
        int r  = i >> 4;            // q row
        int cg = (i & 15) << 2;     // hd group
        float4 v4 = *(const float4*)(Qg + r * NHD + cg);
        Qs[(cg+0)*68 + r] = v4.x * qsc;
        Qs[(cg+1)*68 + r] = v4.y * qsc;
        Qs[(cg+2)*68 + r] = v4.z * qsc;
        Qs[(cg+3)*68 + r] = v4.w * qsc;
    }

    float mrow[4], lrow[4], cacc[4][4];
    #pragma unroll
    for (int i = 0; i < 4; i++) {
        mrow[i] = -1e30f; lrow[i] = 0.f;
        #pragma unroll
        for (int j = 0; j < 4; j++) cacc[i][j] = 0.f;
    }

    for (int kt = 0; kt < NS / 64; kt++) {
        __syncthreads();   // prior PV done reading Ks/Vs; also fences Q load (kt=0)
        const float* Kt = Kg + (size_t)kt * 64 * NHD;
        const float* Vt = Vg + (size_t)kt * 64 * NHD;
        #pragma unroll
        for (int it = 0; it < 4; it++) {
            int i = tid + it * 256;
            int r  = i >> 4;
            int cg = (i & 15) << 2;
            float4 v4 = *(const float4*)(Kt + r * NHD + cg);
            Ks[(cg+0)*68 + r] = v4.x;
            Ks[(cg+1)*68 + r] = v4.y;
            Ks[(cg+2)*68 + r] = v4.z;
            Ks[(cg+3)*68 + r] = v4.w;
            float4 w4 = *(const float4*)(Vt + r * NHD + cg);
            *(float4*)(Vs + r * 64 + cg) = w4;
        }
        __syncthreads();

        // S = Q K^T  (already in log2 scale)
        float s[4][4];
        #pragma unroll
        for (int i = 0; i < 4; i++)
            #pragma unroll
            for (int j = 0; j < 4; j++) s[i][j] = 0.f;
        #pragma unroll 16
        for (int d = 0; d < 64; d++) {
            float qa[4], kb[4];
            *(float4*)qa = *(const float4*)(Qs + d * 68 + ty * 4);
            *(float4*)kb = *(const float4*)(Ks + d * 68 + tx * 4);
            #pragma unroll
            for (int i = 0; i < 4; i++)
                #pragma unroll
                for (int j = 0; j < 4; j++)
                    s[i][j] = fmaf(qa[i], kb[j], s[i][j]);
        }

        // Online softmax per q row (reduce across the 16 tx lanes)
        #pragma unroll
        for (int i = 0; i < 4; i++) {
            float rm = fmaxf(fmaxf(s[i][0], s[i][1]), fmaxf(s[i][2], s[i][3]));
            #pragma unroll
            for (int off = 1; off < 16; off <<= 1)
                rm = fmaxf(rm, __shfl_xor_sync(0xffffffffu, rm, off));
            float mn = fmaxf(mrow[i], rm);
            float alpha = fast_exp2(mrow[i] - mn);
            mrow[i] = mn;
            float rs = 0.f;
            #pragma unroll
            for (int j = 0; j < 4; j++) {
                s[i][j] = fast_exp2(s[i][j] - mn);
                rs += s[i][j];
            }
            #pragma unroll
            for (int off = 1; off < 16; off <<= 1)
                rs += __shfl_xor_sync(0xffffffffu, rs, off);
            lrow[i] = lrow[i] * alpha + rs;
            #pragma unroll
            for (int j = 0; j < 4; j++) cacc[i][j] *= alpha;
            *(float4*)(Ps + (ty*4 + i) * 64 + tx*4) =
                make_float4(s[i][0], s[i][1], s[i][2], s[i][3]);
        }
        __syncwarp();  // P row producers & consumers live in the same warp

        // ctx += P @ V
        #pragma unroll 16
        for (int k = 0; k < 64; k++) {
            float vv[4];
            *(float4*)vv = *(const float4*)(Vs + k * 64 + tx * 4);
            float p0 = Ps[(ty*4+0)*64 + k];
            float p1 = Ps[(ty*4+1)*64 + k];
            float p2 = Ps[(ty*4+2)*64 + k];
            float p3 = Ps[(ty*4+3)*64 + k];
            #pragma unroll
            for (int j = 0; j < 4; j++) {
                cacc[0][j] = fmaf(p0, vv[j], cacc[0][j]);
                cacc[1][j] = fmaf(p1, vv[j], cacc[1][j]);
                cacc[2][j] = fmaf(p2, vv[j], cacc[2][j]);
                cacc[3][j] = fmaf(p3, vv[j], cacc[3][j]);
            }
        }
    }

    // Write ctx in [B, S, H*HD] layout for the output GEMM
    const int b = bh >> 4;
    const int h = bh & 15;
    #pragma unroll
    for (int i = 0; i < 4; i++) {
        float inv = 1.0f / lrow[i];
        int srow = q0 + ty * 4 + i;
        float4 o = make_float4(cacc[i][0]*inv, cacc[i][1]*inv,
                               cacc[i][2]*inv, cacc[i][3]*inv);
        *(float4*)(Og + ((size_t)b * NS + srow) * ND + h * NHD + tx * 4) = o;
    }
}

// ---------------------------------------------------------------------------
extern "C" void kernel_launch(void* const* d_in, const int* in_sizes, int n_in,
                              void* d_out, int out_size)
{
    (void)in_sizes; (void)n_in; (void)out_size;
    const float* x  = (const float*)d_in[0];
    const float* Wq = (const float*)d_in[1];
    const float* bq = (const float*)d_in[2];
    const float* Wk = (const float*)d_in[3];
    const float* bk = (const float*)d_in[4];
    const float* Wv = (const float*)d_in[5];
    const float* bv = (const float*)d_in[6];
    const float* Wo = (const float*)d_in[7];
    const float* bo = (const float*)d_in[8];
    float* out = (float*)d_out;

    float *q, *k, *v, *ctx;
    cudaGetSymbolAddress((void**)&q,   g_q);
    cudaGetSymbolAddress((void**)&k,   g_k);
    cudaGetSymbolAddress((void**)&v,   g_v);
    cudaGetSymbolAddress((void**)&ctx, g_ctx);

    cudaFuncSetAttribute(attn_kernel,
                         cudaFuncAttributeMaxDynamicSharedMemorySize, SMEM_ATTN);

    dim3 gg(ND / 128, NM / 128);        // (8, 64)
    gemm_proj<true ><<<gg, 256>>>(x, Wq, bq, q);
    gemm_proj<true ><<<gg, 256>>>(x, Wk, bk, k);
    gemm_proj<true ><<<gg, 256>>>(x, Wv, bv, v);

    dim3 ga(NS / 64, NB * NH);          // (32, 64)
    attn_kernel<<<ga, 256, SMEM_ATTN>>>(q, k, v, ctx);

    gemm_proj<false><<<gg, 256>>>(ctx, Wo, bo, out);
}